// round 2
// baseline (speedup 1.0000x reference)
#include <cuda_runtime.h>
#include <cstdint>

// Problem constants
#define BB    4
#define SS    2048
#define DM    1024
#define NH    16
#define DH    64
#define TOK   (BB * SS)          // 8192 tokens

// ---------------- scratch (no cudaMalloc allowed) ----------------
__device__ float g_q[TOK * DM];     // [B,H,S,Dh]
__device__ float g_k[TOK * DM];     // [B,H,S,Dh]
__device__ float g_v[TOK * DM];     // [B,H,S,Dh]
__device__ float g_attn[TOK * DM];  // [B,S,D]

// ---------------- helpers ----------------
__device__ __forceinline__ uint32_t f2tf32(float x) {
    uint32_t u;
    asm("cvt.rna.tf32.f32 %0, %1;" : "=r"(u) : "f"(x));
    return u;
}
__device__ __forceinline__ float f2tf32f(float x) {
    return __uint_as_float(f2tf32(x));
}

__device__ __forceinline__ void mma8(float* c, const uint32_t* a, const uint32_t* b) {
    asm volatile(
        "mma.sync.aligned.m16n8k8.row.col.f32.tf32.tf32.f32 "
        "{%0,%1,%2,%3},{%4,%5,%6,%7},{%8,%9},{%0,%1,%2,%3};\n"
        : "+f"(c[0]), "+f"(c[1]), "+f"(c[2]), "+f"(c[3])
        : "r"(a[0]), "r"(a[1]), "r"(a[2]), "r"(a[3]),
          "r"(b[0]), "r"(b[1]));
}

// token,feature -> [B,H,S,Dh] index
__device__ __forceinline__ int qkv_idx(int tok, int n) {
    int b = tok >> 11, s = tok & 2047;
    int h = n >> 6, dh = n & 63;
    return (((b * NH + h) * SS) + s) * DH + dh;
}

// ---------------- TF32 GEMM: C[M=8192,N=1024] = A[M,K=1024] * W[N,K]^T + bias ----------------
// mode 0: write to [B,H,S,Dh] scratch layout; mode 1: write row-major [T,N]
#define GPA 36  // smem pitch (floats) -> conflict-free frag loads

__global__ void __launch_bounds__(256, 2)
gemm_tf32(const float* __restrict__ A, const float* __restrict__ W,
          const float* __restrict__ bias, float* __restrict__ out, int mode)
{
    __shared__ float As[128 * GPA];
    __shared__ float Bs[128 * GPA];

    const int tid  = threadIdx.x;
    const int warp = tid >> 5, lane = tid & 31;
    const int g = lane >> 2, t = lane & 3;
    const int wm = warp >> 2, wn = warp & 3;
    const int bm = blockIdx.x * 128, bn = blockIdx.y * 128;

    float acc[4][4][4];
#pragma unroll
    for (int i = 0; i < 4; i++)
#pragma unroll
        for (int j = 0; j < 4; j++)
#pragma unroll
            for (int e = 0; e < 4; e++) acc[i][j][e] = 0.f;

    for (int kc = 0; kc < DM; kc += 32) {
        __syncthreads();
#pragma unroll
        for (int it = 0; it < 4; it++) {
            int l = tid + it * 256;
            int r = l >> 3, c = (l & 7) << 2;
            float4 va = *(const float4*)(A + (size_t)(bm + r) * DM + kc + c);
            As[r * GPA + c + 0] = f2tf32f(va.x);
            As[r * GPA + c + 1] = f2tf32f(va.y);
            As[r * GPA + c + 2] = f2tf32f(va.z);
            As[r * GPA + c + 3] = f2tf32f(va.w);
            float4 vb = *(const float4*)(W + (size_t)(bn + r) * DM + kc + c);
            Bs[r * GPA + c + 0] = f2tf32f(vb.x);
            Bs[r * GPA + c + 1] = f2tf32f(vb.y);
            Bs[r * GPA + c + 2] = f2tf32f(vb.z);
            Bs[r * GPA + c + 3] = f2tf32f(vb.w);
        }
        __syncthreads();
#pragma unroll
        for (int ks = 0; ks < 32; ks += 8) {
            uint32_t af[4][4], bf[4][2];
#pragma unroll
            for (int i = 0; i < 4; i++) {
                int r0 = wm * 64 + i * 16 + g;
                af[i][0] = __float_as_uint(As[r0 * GPA + ks + t]);
                af[i][1] = __float_as_uint(As[(r0 + 8) * GPA + ks + t]);
                af[i][2] = __float_as_uint(As[r0 * GPA + ks + t + 4]);
                af[i][3] = __float_as_uint(As[(r0 + 8) * GPA + ks + t + 4]);
            }
#pragma unroll
            for (int j = 0; j < 4; j++) {
                int n0 = wn * 32 + j * 8 + g;
                bf[j][0] = __float_as_uint(Bs[n0 * GPA + ks + t]);
                bf[j][1] = __float_as_uint(Bs[n0 * GPA + ks + t + 4]);
            }
#pragma unroll
            for (int i = 0; i < 4; i++)
#pragma unroll
                for (int j = 0; j < 4; j++) mma8(acc[i][j], af[i], bf[j]);
        }
    }

    // epilogue
#pragma unroll
    for (int i = 0; i < 4; i++) {
#pragma unroll
        for (int j = 0; j < 4; j++) {
            int row0 = bm + wm * 64 + i * 16 + g;
            int col0 = bn + wn * 32 + j * 8 + 2 * t;
            float b0 = bias[col0], b1 = bias[col0 + 1];
            if (mode == 0) {
                out[qkv_idx(row0, col0)]         = acc[i][j][0] + b0;
                out[qkv_idx(row0, col0 + 1)]     = acc[i][j][1] + b1;
                out[qkv_idx(row0 + 8, col0)]     = acc[i][j][2] + b0;
                out[qkv_idx(row0 + 8, col0 + 1)] = acc[i][j][3] + b1;
            } else {
                out[(size_t)row0 * DM + col0]           = acc[i][j][0] + b0;
                out[(size_t)row0 * DM + col0 + 1]       = acc[i][j][1] + b1;
                out[(size_t)(row0 + 8) * DM + col0]     = acc[i][j][2] + b0;
                out[(size_t)(row0 + 8) * DM + col0 + 1] = acc[i][j][3] + b1;
            }
        }
    }
}

// ---------------- Flash attention (TF32 mma), per (b,h), 128 q rows / CTA ----------------
#define KSP 68   // K smem pitch (floats)
#define VSP 72   // V smem pitch
#define PSP 132  // P smem pitch
#define ATTN_SMEM_FLOATS (128 * KSP + 128 * VSP + 128 * PSP)
#define ATTN_SMEM_BYTES  (ATTN_SMEM_FLOATS * 4)

__global__ void __launch_bounds__(256, 1)
attn_kernel(const float* __restrict__ q, const float* __restrict__ k,
            const float* __restrict__ v, float* __restrict__ out)
{
    extern __shared__ float sm[];
    float* Ks = sm;
    float* Vs = sm + 128 * KSP;
    float* Ps = Vs + 128 * VSP;

    const int tid = threadIdx.x, warp = tid >> 5, lane = tid & 31;
    const int g = lane >> 2, t = lane & 3;
    const int bh = blockIdx.y, qt = blockIdx.x;
    const int band = warp * 16;

    const float* qb = q + (size_t)bh * SS * DH;
    const float* kb = k + (size_t)bh * SS * DH;
    const float* vb = v + (size_t)bh * SS * DH;

    // fold softmax scale and log2(e) into Q so logits come out in log2 domain
    const float qscale = 0.125f * 1.4426950408889634f;

    uint32_t qf[8][4];
    {
        int r0 = qt * 128 + band + g;
#pragma unroll
        for (int kk = 0; kk < 8; kk++) {
            int c = kk * 8 + t;
            qf[kk][0] = f2tf32(qb[(size_t)r0 * DH + c] * qscale);
            qf[kk][1] = f2tf32(qb[(size_t)(r0 + 8) * DH + c] * qscale);
            qf[kk][2] = f2tf32(qb[(size_t)r0 * DH + c + 4] * qscale);
            qf[kk][3] = f2tf32(qb[(size_t)(r0 + 8) * DH + c + 4] * qscale);
        }
    }

    float m0 = -INFINITY, m1 = -INFINITY, l0 = 0.f, l1 = 0.f;
    float oa[8][4];
#pragma unroll
    for (int j = 0; j < 8; j++)
#pragma unroll
        for (int e = 0; e < 4; e++) oa[j][e] = 0.f;

    float* prow0 = Ps + (band + g) * PSP;
    float* prow1 = Ps + (band + g + 8) * PSP;

    for (int kv = 0; kv < 16; kv++) {
        __syncthreads();
        const float* kt = kb + (size_t)kv * 128 * DH;
        const float* vt = vb + (size_t)kv * 128 * DH;
#pragma unroll
        for (int it = 0; it < 8; it++) {
            int l = tid + it * 256;
            int r = l >> 4, c = (l & 15) << 2;
            float4 a = *(const float4*)(kt + (size_t)r * DH + c);
            Ks[r * KSP + c + 0] = f2tf32f(a.x);
            Ks[r * KSP + c + 1] = f2tf32f(a.y);
            Ks[r * KSP + c + 2] = f2tf32f(a.z);
            Ks[r * KSP + c + 3] = f2tf32f(a.w);
            float4 b4 = *(const float4*)(vt + (size_t)r * DH + c);
            Vs[r * VSP + c + 0] = f2tf32f(b4.x);
            Vs[r * VSP + c + 1] = f2tf32f(b4.y);
            Vs[r * VSP + c + 2] = f2tf32f(b4.z);
            Vs[r * VSP + c + 3] = f2tf32f(b4.w);
        }
        __syncthreads();

        // S = Q * K^T  (log2-domain logits)
        float sf[16][4];
#pragma unroll
        for (int j = 0; j < 16; j++)
#pragma unroll
            for (int e = 0; e < 4; e++) sf[j][e] = 0.f;
#pragma unroll
        for (int kk = 0; kk < 8; kk++) {
#pragma unroll
            for (int j = 0; j < 16; j++) {
                uint32_t bb[2];
                bb[0] = __float_as_uint(Ks[(j * 8 + g) * KSP + kk * 8 + t]);
                bb[1] = __float_as_uint(Ks[(j * 8 + g) * KSP + kk * 8 + t + 4]);
                mma8(sf[j], qf[kk], bb);
            }
        }

        // online softmax (rows band+g and band+g+8)
        float mt0 = -INFINITY, mt1 = -INFINITY;
#pragma unroll
        for (int j = 0; j < 16; j++) {
            mt0 = fmaxf(mt0, fmaxf(sf[j][0], sf[j][1]));
            mt1 = fmaxf(mt1, fmaxf(sf[j][2], sf[j][3]));
        }
        mt0 = fmaxf(mt0, __shfl_xor_sync(0xffffffffu, mt0, 1));
        mt0 = fmaxf(mt0, __shfl_xor_sync(0xffffffffu, mt0, 2));
        mt1 = fmaxf(mt1, __shfl_xor_sync(0xffffffffu, mt1, 1));
        mt1 = fmaxf(mt1, __shfl_xor_sync(0xffffffffu, mt1, 2));

        float mn0 = fmaxf(m0, mt0), mn1 = fmaxf(m1, mt1);
        float al0 = exp2f(m0 - mn0), al1 = exp2f(m1 - mn1);

        float rs0 = 0.f, rs1 = 0.f;
#pragma unroll
        for (int j = 0; j < 16; j++) {
            float p0 = exp2f(sf[j][0] - mn0);
            float p1 = exp2f(sf[j][1] - mn0);
            float p2 = exp2f(sf[j][2] - mn1);
            float p3 = exp2f(sf[j][3] - mn1);
            rs0 += p0 + p1;
            rs1 += p2 + p3;
            int c0 = j * 8 + 2 * t;
            prow0[c0]     = f2tf32f(p0);
            prow0[c0 + 1] = f2tf32f(p1);
            prow1[c0]     = f2tf32f(p2);
            prow1[c0 + 1] = f2tf32f(p3);
        }
        rs0 += __shfl_xor_sync(0xffffffffu, rs0, 1);
        rs0 += __shfl_xor_sync(0xffffffffu, rs0, 2);
        rs1 += __shfl_xor_sync(0xffffffffu, rs1, 1);
        rs1 += __shfl_xor_sync(0xffffffffu, rs1, 2);

        l0 = l0 * al0 + rs0;
        l1 = l1 * al1 + rs1;
        m0 = mn0;
        m1 = mn1;
#pragma unroll
        for (int j = 0; j < 8; j++) {
            oa[j][0] *= al0; oa[j][1] *= al0;
            oa[j][2] *= al1; oa[j][3] *= al1;
        }
        __syncwarp();

        // O += P * V
#pragma unroll
        for (int kk = 0; kk < 16; kk++) {
            uint32_t af[4];
            af[0] = __float_as_uint(prow0[kk * 8 + t]);
            af[1] = __float_as_uint(prow1[kk * 8 + t]);
            af[2] = __float_as_uint(prow0[kk * 8 + t + 4]);
            af[3] = __float_as_uint(prow1[kk * 8 + t + 4]);
#pragma unroll
            for (int j = 0; j < 8; j++) {
                uint32_t bb[2];
                bb[0] = __float_as_uint(Vs[(kk * 8 + t) * VSP + j * 8 + g]);
                bb[1] = __float_as_uint(Vs[(kk * 8 + t + 4) * VSP + j * 8 + g]);
                mma8(oa[j], af, bb);
            }
        }
    }

    float i0 = 1.f / l0, i1 = 1.f / l1;
    int b = bh >> 4, h = bh & 15;
    int tr0 = b * SS + qt * 128 + band + g;
    float* ob0 = out + (size_t)tr0 * DM + h * DH;
    float* ob1 = out + (size_t)(tr0 + 8) * DM + h * DH;
#pragma unroll
    for (int j = 0; j < 8; j++) {
        int c = j * 8 + 2 * t;
        ob0[c]     = oa[j][0] * i0;
        ob0[c + 1] = oa[j][1] * i0;
        ob1[c]     = oa[j][2] * i1;
        ob1[c + 1] = oa[j][3] * i1;
    }
}

// ---------------- launcher ----------------
extern "C" void kernel_launch(void* const* d_in, const int* in_sizes, int n_in,
                              void* d_out, int out_size)
{
    const float* Q  = (const float*)d_in[0];
    const float* K  = (const float*)d_in[1];
    const float* V  = (const float*)d_in[2];
    const float* Wq = (const float*)d_in[3];
    const float* bq = (const float*)d_in[4];
    const float* Wk = (const float*)d_in[5];
    const float* bk = (const float*)d_in[6];
    const float* Wv = (const float*)d_in[7];
    const float* bv = (const float*)d_in[8];
    const float* Wo = (const float*)d_in[9];
    const float* bo = (const float*)d_in[10];

    float *qp, *kp, *vp, *ap;
    cudaGetSymbolAddress((void**)&qp, g_q);
    cudaGetSymbolAddress((void**)&kp, g_k);
    cudaGetSymbolAddress((void**)&vp, g_v);
    cudaGetSymbolAddress((void**)&ap, g_attn);

    cudaFuncSetAttribute(attn_kernel, cudaFuncAttributeMaxDynamicSharedMemorySize,
                         ATTN_SMEM_BYTES);

    dim3 ggrid(TOK / 128, DM / 128);  // 64 x 8
    gemm_tf32<<<ggrid, 256>>>(Q, Wq, bq, qp, 0);
    gemm_tf32<<<ggrid, 256>>>(K, Wk, bk, kp, 0);
    gemm_tf32<<<ggrid, 256>>>(V, Wv, bv, vp, 0);

    dim3 agrid(SS / 128, BB * NH);    // 16 x 64
    attn_kernel<<<agrid, 256, ATTN_SMEM_BYTES>>>(qp, kp, vp, ap);

    gemm_tf32<<<ggrid, 256>>>(ap, Wo, bo, (float*)d_out, 1);
}

// round 5
// speedup vs baseline: 1.1418x; 1.1418x over previous
#include <cuda_runtime.h>
#include <cstdint>

// Problem constants
#define BB    4
#define SS    2048
#define DM    1024
#define NH    16
#define DH    64
#define TOK   (BB * SS)          // 8192 tokens

// ---------------- scratch (no cudaMalloc allowed) ----------------
__device__ float g_q[TOK * DM];     // [B,H,S,Dh]  (tf32-rounded)
__device__ float g_k[TOK * DM];     // [B,H,S,Dh]  (tf32-rounded)
__device__ float g_v[TOK * DM];     // [B,H,S,Dh]  (tf32-rounded)
__device__ float g_attn[TOK * DM];  // [B,S,D]     (tf32-rounded by attn epilogue)
__device__ float g_qin[TOK * DM];   // RNA-rounded inputs
__device__ float g_kin[TOK * DM];
__device__ float g_vin[TOK * DM];
__device__ float g_wq[DM * DM];     // RNA-rounded weights
__device__ float g_wk[DM * DM];
__device__ float g_wv[DM * DM];
__device__ float g_wo[DM * DM];

// ---------------- helpers ----------------
__device__ __forceinline__ uint32_t f2tf32(float x) {
    uint32_t u;
    asm("cvt.rna.tf32.f32 %0, %1;" : "=r"(u) : "f"(x));
    return u;
}
__device__ __forceinline__ float f2tf32f(float x) {
    return __uint_as_float(f2tf32(x));
}

__device__ __forceinline__ uint32_t smem_u32(const void* p) {
    uint32_t a;
    asm("{ .reg .u64 t; cvta.to.shared.u64 t, %1; cvt.u32.u64 %0, t; }" : "=r"(a) : "l"(p));
    return a;
}

__device__ __forceinline__ void cpasync16(uint32_t dst, const void* src) {
    asm volatile("cp.async.cg.shared.global [%0], [%1], 16;" :: "r"(dst), "l"(src));
}
#define CP_COMMIT()  asm volatile("cp.async.commit_group;" ::: "memory")
#define CP_WAIT(n)   asm volatile("cp.async.wait_group " #n ";" ::: "memory")

__device__ __forceinline__ void mma8(float* c, const uint32_t* a, const uint32_t* b) {
    asm volatile(
        "mma.sync.aligned.m16n8k8.row.col.f32.tf32.tf32.f32 "
        "{%0,%1,%2,%3},{%4,%5,%6,%7},{%8,%9},{%0,%1,%2,%3};\n"
        : "+f"(c[0]), "+f"(c[1]), "+f"(c[2]), "+f"(c[3])
        : "r"(a[0]), "r"(a[1]), "r"(a[2]), "r"(a[3]),
          "r"(b[0]), "r"(b[1]));
}

// ---------------- RNA tf32 rounding pass ----------------
__global__ void round_k(const float* __restrict__ s, float* __restrict__ d, int n4) {
    int i = blockIdx.x * blockDim.x + threadIdx.x;
    if (i < n4) {
        float4 v = ((const float4*)s)[i];
        v.x = f2tf32f(v.x); v.y = f2tf32f(v.y);
        v.z = f2tf32f(v.z); v.w = f2tf32f(v.w);
        ((float4*)d)[i] = v;
    }
}

// ---------------- TF32 GEMM (mma.sync, cp.async 3-stage pipeline) ----------------
// C[8192,1024] = A[8192,1024(K-major)] @ W[1024,1024(K-major)]^T + bias
// CTA tile: M=128, N=128, K-step 32. Operands pre-rounded to tf32 in gmem.
// Smem: per stage A 16KB + B 16KB, 3 stages = 96KB; 16B-chunk XOR swizzle.
// mode 0: scatter into [B,H,S,Dh] (tf32-rounded); mode 1: row-major [T,N] raw.
#define GSTAGE_BYTES 32768
#define GSMEM        (3 * GSTAGE_BYTES)   // 98304

__global__ void __launch_bounds__(256, 2)
gemm_ms(const float* __restrict__ A, const float* __restrict__ W,
        const float* __restrict__ bias, float* __restrict__ out, int mode)
{
    extern __shared__ char smc[];
    const uint32_t sb = smem_u32(smc);
    const int tid  = threadIdx.x;
    const int warp = tid >> 5, lane = tid & 31;
    const int g = lane >> 2, t = lane & 3;
    const int wm = warp >> 2, wn = warp & 3;
    const int bm = blockIdx.y * 128, bn = blockIdx.x * 128;

    const float* Ab = A + (size_t)bm * DM;
    const float* Wb = W + (size_t)bn * DM;

    float acc[4][4][4];
#pragma unroll
    for (int i = 0; i < 4; i++)
#pragma unroll
        for (int j = 0; j < 4; j++)
#pragma unroll
            for (int e = 0; e < 4; e++) acc[i][j][e] = 0.f;

    // fill one 128x32 A tile + 128x32 B tile into stage stg (chunk-XOR swizzle)
#define LOAD_TILE(kt, stg)                                                       \
    do {                                                                         \
        uint32_t bA = sb + (stg) * GSTAGE_BYTES;                                 \
        uint32_t bBs = bA + 16384;                                               \
        int kc = (kt) * 32;                                                      \
        _Pragma("unroll")                                                        \
        for (int i_ = 0; i_ < 4; i_++) {                                         \
            int id = tid + i_ * 256;                                             \
            int r_ = id >> 3, c4 = id & 7;                                       \
            uint32_t doff = (uint32_t)(r_ * 128 + ((c4 ^ (r_ & 7)) << 4));       \
            cpasync16(bA + doff,  Ab + (size_t)r_ * DM + kc + c4 * 4);           \
            cpasync16(bBs + doff, Wb + (size_t)r_ * DM + kc + c4 * 4);           \
        }                                                                        \
    } while (0)

    LOAD_TILE(0, 0); CP_COMMIT();
    LOAD_TILE(1, 1); CP_COMMIT();
    LOAD_TILE(2, 2); CP_COMMIT();

    for (int tt = 0; tt < 32; tt++) {
        CP_WAIT(2);
        __syncthreads();
        const int stg = tt % 3;
        const float* sA = (const float*)(smc + stg * GSTAGE_BYTES);
        const float* sB = sA + 4096;
#pragma unroll
        for (int k8 = 0; k8 < 4; k8++) {
            const int ch0 = (((k8 * 2)     ^ g) & 7) << 2;
            const int ch1 = (((k8 * 2 + 1) ^ g) & 7) << 2;
            uint32_t af[4][4], bf[4][2];
#pragma unroll
            for (int i = 0; i < 4; i++) {
                int r0 = (wm * 64 + i * 16 + g) * 32;
                af[i][0] = __float_as_uint(sA[r0 + ch0 + t]);
                af[i][1] = __float_as_uint(sA[r0 + 256 + ch0 + t]);   // +8 rows
                af[i][2] = __float_as_uint(sA[r0 + ch1 + t]);
                af[i][3] = __float_as_uint(sA[r0 + 256 + ch1 + t]);
            }
#pragma unroll
            for (int j = 0; j < 4; j++) {
                int n0 = (wn * 32 + j * 8 + g) * 32;
                bf[j][0] = __float_as_uint(sB[n0 + ch0 + t]);
                bf[j][1] = __float_as_uint(sB[n0 + ch1 + t]);
            }
#pragma unroll
            for (int i = 0; i < 4; i++)
#pragma unroll
                for (int j = 0; j < 4; j++) mma8(acc[i][j], af[i], bf[j]);
        }
        __syncthreads();
        if (tt + 3 < 32) LOAD_TILE(tt + 3, (tt + 3) % 3);
        CP_COMMIT();   // always commit (possibly empty) to keep group counts uniform
    }
#undef LOAD_TILE

    // epilogue
#pragma unroll
    for (int i = 0; i < 4; i++) {
#pragma unroll
        for (int j = 0; j < 4; j++) {
            int row0 = bm + wm * 64 + i * 16 + g;
            int col0 = bn + wn * 32 + j * 8 + 2 * t;
            float b0 = bias[col0], b1 = bias[col0 + 1];
            if (mode == 1) {
                out[(size_t)row0 * DM + col0]           = acc[i][j][0] + b0;
                out[(size_t)row0 * DM + col0 + 1]       = acc[i][j][1] + b1;
                out[(size_t)(row0 + 8) * DM + col0]     = acc[i][j][2] + b0;
                out[(size_t)(row0 + 8) * DM + col0 + 1] = acc[i][j][3] + b1;
            } else {
                // scatter into [B,H,S,Dh], tf32-rounded for the attn consumers
                int h = col0 >> 6, dh = col0 & 63;
                int b = row0 >> 11, s = row0 & 2047;
                size_t base0 = ((((size_t)b * NH + h) * SS) + s) * DH + dh;
                size_t base1 = base0 + 8 * DH;           // row0+8: same b (128-row tile)
                out[base0]     = f2tf32f(acc[i][j][0] + b0);
                out[base0 + 1] = f2tf32f(acc[i][j][1] + b1);
                out[base1]     = f2tf32f(acc[i][j][2] + b0);
                out[base1 + 1] = f2tf32f(acc[i][j][3] + b1);
            }
        }
    }
}

// ---------------- Flash attention (TF32 mma.sync), double-buffered cp.async ----------------
#define KSP 68   // 272B rows (16B multiple)
#define VSP 72   // 288B rows
#define PSP 132
#define BUF_FLOATS (128 * (KSP + VSP))           // 17920
#define ATTN_SMEM_FLOATS (2 * BUF_FLOATS + 128 * PSP)
#define ATTN_SMEM_BYTES  (ATTN_SMEM_FLOATS * 4)  // 210944

__global__ void __launch_bounds__(256, 1)
attn_kernel(const float* __restrict__ q, const float* __restrict__ k,
            const float* __restrict__ v, float* __restrict__ out)
{
    extern __shared__ float sm[];
    const uint32_t sba = smem_u32(sm);
    float* Ps = sm + 2 * BUF_FLOATS;

    const int tid = threadIdx.x, warp = tid >> 5, lane = tid & 31;
    const int g = lane >> 2, t = lane & 3;
    const int bh = blockIdx.y, qt = blockIdx.x;
    const int band = warp * 16;

    const float* qb = q + (size_t)bh * SS * DH;
    const float* kb = k + (size_t)bh * SS * DH;
    const float* vb = v + (size_t)bh * SS * DH;

    // K/V are pre-rounded to tf32; raw cp.async copy into double-buffered smem
#define AFILL(tile, buf)                                                        \
    do {                                                                        \
        const float* kt_ = kb + (size_t)(tile) * 128 * DH;                      \
        const float* vt_ = vb + (size_t)(tile) * 128 * DH;                      \
        uint32_t kb_ = sba + (buf) * (BUF_FLOATS * 4);                          \
        uint32_t vb_ = kb_ + 128 * KSP * 4;                                     \
        _Pragma("unroll")                                                       \
        for (int i_ = 0; i_ < 8; i_++) {                                        \
            int id = tid + i_ * 256;                                            \
            int r_ = id >> 4, c_ = id & 15;                                     \
            cpasync16(kb_ + r_ * 272 + c_ * 16, kt_ + r_ * 64 + c_ * 4);        \
            cpasync16(vb_ + r_ * 288 + c_ * 16, vt_ + r_ * 64 + c_ * 4);        \
        }                                                                       \
    } while (0)

    const float qscale = 0.125f * 1.4426950408889634f;

    uint32_t qf[8][4];
    {
        int r0 = qt * 128 + band + g;
#pragma unroll
        for (int kk = 0; kk < 8; kk++) {
            int c = kk * 8 + t;
            qf[kk][0] = f2tf32(qb[(size_t)r0 * DH + c] * qscale);
            qf[kk][1] = f2tf32(qb[(size_t)(r0 + 8) * DH + c] * qscale);
            qf[kk][2] = f2tf32(qb[(size_t)r0 * DH + c + 4] * qscale);
            qf[kk][3] = f2tf32(qb[(size_t)(r0 + 8) * DH + c + 4] * qscale);
        }
    }

    float m0 = -INFINITY, m1 = -INFINITY, l0 = 0.f, l1 = 0.f;
    float oa[8][4];
#pragma unroll
    for (int j = 0; j < 8; j++)
#pragma unroll
        for (int e = 0; e < 4; e++) oa[j][e] = 0.f;

    float* prow0 = Ps + (band + g) * PSP;
    float* prow1 = Ps + (band + g + 8) * PSP;

    AFILL(0, 0); CP_COMMIT();

    for (int kv = 0; kv < 16; kv++) {
        if (kv < 15) { AFILL(kv + 1, (kv + 1) & 1); CP_COMMIT(); CP_WAIT(1); }
        else         { CP_WAIT(0); }
        __syncthreads();

        const float* Ks = sm + (kv & 1) * BUF_FLOATS;
        const float* Vs = Ks + 128 * KSP;

        // S = Q * K^T  (log2-domain logits)
        float sf[16][4];
#pragma unroll
        for (int j = 0; j < 16; j++)
#pragma unroll
            for (int e = 0; e < 4; e++) sf[j][e] = 0.f;
#pragma unroll
        for (int kk = 0; kk < 8; kk++) {
#pragma unroll
            for (int j = 0; j < 16; j++) {
                uint32_t bbf[2];
                bbf[0] = __float_as_uint(Ks[(j * 8 + g) * KSP + kk * 8 + t]);
                bbf[1] = __float_as_uint(Ks[(j * 8 + g) * KSP + kk * 8 + t + 4]);
                mma8(sf[j], qf[kk], bbf);
            }
        }

        // online softmax
        float mt0 = -INFINITY, mt1 = -INFINITY;
#pragma unroll
        for (int j = 0; j < 16; j++) {
            mt0 = fmaxf(mt0, fmaxf(sf[j][0], sf[j][1]));
            mt1 = fmaxf(mt1, fmaxf(sf[j][2], sf[j][3]));
        }
        mt0 = fmaxf(mt0, __shfl_xor_sync(0xffffffffu, mt0, 1));
        mt0 = fmaxf(mt0, __shfl_xor_sync(0xffffffffu, mt0, 2));
        mt1 = fmaxf(mt1, __shfl_xor_sync(0xffffffffu, mt1, 1));
        mt1 = fmaxf(mt1, __shfl_xor_sync(0xffffffffu, mt1, 2));

        float mn0 = fmaxf(m0, mt0), mn1 = fmaxf(m1, mt1);
        float al0 = exp2f(m0 - mn0), al1 = exp2f(m1 - mn1);

        float rs0 = 0.f, rs1 = 0.f;
#pragma unroll
        for (int j = 0; j < 16; j++) {
            float p0 = exp2f(sf[j][0] - mn0);
            float p1 = exp2f(sf[j][1] - mn0);
            float p2 = exp2f(sf[j][2] - mn1);
            float p3 = exp2f(sf[j][3] - mn1);
            rs0 += p0 + p1;
            rs1 += p2 + p3;
            int c0 = j * 8 + 2 * t;
            prow0[c0]     = f2tf32f(p0);
            prow0[c0 + 1] = f2tf32f(p1);
            prow1[c0]     = f2tf32f(p2);
            prow1[c0 + 1] = f2tf32f(p3);
        }
        rs0 += __shfl_xor_sync(0xffffffffu, rs0, 1);
        rs0 += __shfl_xor_sync(0xffffffffu, rs0, 2);
        rs1 += __shfl_xor_sync(0xffffffffu, rs1, 1);
        rs1 += __shfl_xor_sync(0xffffffffu, rs1, 2);

        l0 = l0 * al0 + rs0;
        l1 = l1 * al1 + rs1;
        m0 = mn0;
        m1 = mn1;
#pragma unroll
        for (int j = 0; j < 8; j++) {
            oa[j][0] *= al0; oa[j][1] *= al0;
            oa[j][2] *= al1; oa[j][3] *= al1;
        }
        __syncwarp();

        // O += P * V
#pragma unroll
        for (int kk = 0; kk < 16; kk++) {
            uint32_t af[4];
            af[0] = __float_as_uint(prow0[kk * 8 + t]);
            af[1] = __float_as_uint(prow1[kk * 8 + t]);
            af[2] = __float_as_uint(prow0[kk * 8 + t + 4]);
            af[3] = __float_as_uint(prow1[kk * 8 + t + 4]);
#pragma unroll
            for (int j = 0; j < 8; j++) {
                uint32_t bbf[2];
                bbf[0] = __float_as_uint(Vs[(kk * 8 + t) * VSP + j * 8 + g]);
                bbf[1] = __float_as_uint(Vs[(kk * 8 + t + 4) * VSP + j * 8 + g]);
                mma8(oa[j], af, bbf);
            }
        }
        __syncthreads();   // release the buffer the next iter's prefetch overwrites
    }
#undef AFILL

    float i0 = 1.f / l0, i1 = 1.f / l1;
    int b = bh >> 4, h = bh & 15;
    int tr0 = b * SS + qt * 128 + band + g;
    float* ob0 = out + (size_t)tr0 * DM + h * DH;
    float* ob1 = out + (size_t)(tr0 + 8) * DM + h * DH;
#pragma unroll
    for (int j = 0; j < 8; j++) {
        int c = j * 8 + 2 * t;
        // tf32-rounded so the output GEMM consumes exact tf32 values
        ob0[c]     = f2tf32f(oa[j][0] * i0);
        ob0[c + 1] = f2tf32f(oa[j][1] * i0);
        ob1[c]     = f2tf32f(oa[j][2] * i1);
        ob1[c + 1] = f2tf32f(oa[j][3] * i1);
    }
}

// ---------------- launcher ----------------
extern "C" void kernel_launch(void* const* d_in, const int* in_sizes, int n_in,
                              void* d_out, int out_size)
{
    const float* Q  = (const float*)d_in[0];
    const float* K  = (const float*)d_in[1];
    const float* V  = (const float*)d_in[2];
    const float* Wq = (const float*)d_in[3];
    const float* bq = (const float*)d_in[4];
    const float* Wk = (const float*)d_in[5];
    const float* bk = (const float*)d_in[6];
    const float* Wv = (const float*)d_in[7];
    const float* bv = (const float*)d_in[8];
    const float* Wo = (const float*)d_in[9];
    const float* bo = (const float*)d_in[10];

    float *qp, *kp, *vp, *ap, *qi, *ki, *vi, *wq, *wk, *wv, *wo;
    cudaGetSymbolAddress((void**)&qp, g_q);
    cudaGetSymbolAddress((void**)&kp, g_k);
    cudaGetSymbolAddress((void**)&vp, g_v);
    cudaGetSymbolAddress((void**)&ap, g_attn);
    cudaGetSymbolAddress((void**)&qi, g_qin);
    cudaGetSymbolAddress((void**)&ki, g_kin);
    cudaGetSymbolAddress((void**)&vi, g_vin);
    cudaGetSymbolAddress((void**)&wq, g_wq);
    cudaGetSymbolAddress((void**)&wk, g_wk);
    cudaGetSymbolAddress((void**)&wv, g_wv);
    cudaGetSymbolAddress((void**)&wo, g_wo);

    cudaFuncSetAttribute(attn_kernel, cudaFuncAttributeMaxDynamicSharedMemorySize,
                         ATTN_SMEM_BYTES);
    cudaFuncSetAttribute(gemm_ms, cudaFuncAttributeMaxDynamicSharedMemorySize, GSMEM);

    // RNA-round inputs + weights to tf32 (makes cp.async raw copies exact)
    const int n4i = TOK * DM / 4;
    const int n4w = DM * DM / 4;
    round_k<<<n4i / 256, 256>>>(Q, qi, n4i);
    round_k<<<n4i / 256, 256>>>(K, ki, n4i);
    round_k<<<n4i / 256, 256>>>(V, vi, n4i);
    round_k<<<n4w / 256, 256>>>(Wq, wq, n4w);
    round_k<<<n4w / 256, 256>>>(Wk, wk, n4w);
    round_k<<<n4w / 256, 256>>>(Wv, wv, n4w);
    round_k<<<n4w / 256, 256>>>(Wo, wo, n4w);

    dim3 ggrid(DM / 128, TOK / 128);  // (8, 64)
    gemm_ms<<<ggrid, 256, GSMEM>>>(qi, wq, bq, qp, 0);
    gemm_ms<<<ggrid, 256, GSMEM>>>(ki, wk, bk, kp, 0);
    gemm_ms<<<ggrid, 256, GSMEM>>>(vi, wv, bv, vp, 0);

    dim3 agrid(SS / 128, BB * NH);    // (16, 64)
    attn_kernel<<<agrid, 256, ATTN_SMEM_BYTES>>>(qp, kp, vp, ap);

    gemm_ms<<<ggrid, 256, GSMEM>>>(ap, wo, bo, (float*)d_out, 1);
}